// round 13
// baseline (speedup 1.0000x reference)
#include <cuda_runtime.h>
#include <cstdint>

#define H      16384
#define BATCH  512
#define INSZ   2048
#define KSEL   64
#define DECAY  0.95f

#define NTH    1024
#define CAP    1024

__device__ float g_enc[(size_t)BATCH * H];   // 32 MB scratch (no-alloc rule)

// ---------------------------------------------------------------------------
__global__ void zero_out_kernel(float4* __restrict__ out, int n4) {
    int i = blockIdx.x * blockDim.x + threadIdx.x;
    if (i < n4) out[i] = make_float4(0.f, 0.f, 0.f, 0.f);
}

// ---------------------------------------------------------------------------
// fp32 GEMM  C[m][n] = sum_k A[m][k] * W[n][k]; 128x128 tile, BK=16
// (round-8 baseline version)
// ---------------------------------------------------------------------------
#define GBM 128
#define GBN 128
#define GBK 16

__global__ void __launch_bounds__(256) sgemm_nt_kernel(
    const float* __restrict__ A, const float* __restrict__ W)
{
    __shared__ float As[GBK][GBM];
    __shared__ float Bs[GBK][GBN];

    const int bn = blockIdx.x * GBN, bm = blockIdx.y * GBM;
    const int tid = threadIdx.x, tx = tid & 15, ty = tid >> 4;

    float acc[8][8];
#pragma unroll
    for (int i = 0; i < 8; i++)
#pragma unroll
        for (int j = 0; j < 8; j++) acc[i][j] = 0.f;

    for (int k0 = 0; k0 < INSZ; k0 += GBK) {
#pragma unroll
        for (int l = 0; l < 2; l++) {
            int q = tid + 256 * l, row = q >> 2, kk = (q & 3) * 4;
            float4 v = *(const float4*)&A[(bm + row) * INSZ + k0 + kk];
            As[kk][row] = v.x; As[kk + 1][row] = v.y;
            As[kk + 2][row] = v.z; As[kk + 3][row] = v.w;
        }
#pragma unroll
        for (int l = 0; l < 2; l++) {
            int q = tid + 256 * l, row = q >> 2, kk = (q & 3) * 4;
            float4 v = *(const float4*)&W[(bn + row) * INSZ + k0 + kk];
            Bs[kk][row] = v.x; Bs[kk + 1][row] = v.y;
            Bs[kk + 2][row] = v.z; Bs[kk + 3][row] = v.w;
        }
        __syncthreads();
#pragma unroll
        for (int k = 0; k < GBK; k++) {
            float a[8], b[8];
#pragma unroll
            for (int i = 0; i < 8; i++) a[i] = As[k][ty * 8 + i];
#pragma unroll
            for (int i = 0; i < 8; i++) b[i] = Bs[k][tx * 8 + i];
#pragma unroll
            for (int i = 0; i < 8; i++)
#pragma unroll
                for (int j = 0; j < 8; j++)
                    acc[i][j] = fmaf(a[i], b[j], acc[i][j]);
        }
        __syncthreads();
    }
#pragma unroll
    for (int i = 0; i < 8; i++) {
        int m = bm + ty * 8 + i;
#pragma unroll
        for (int j = 0; j < 8; j += 4)
            *(float4*)&g_enc[(size_t)m * H + bn + tx * 8 + j] =
                make_float4(acc[i][j], acc[i][j+1], acc[i][j+2], acc[i][j+3]);
    }
}

// ---------------------------------------------------------------------------
// Persistent single-CTA scan — shared-atomic-free hot path.
// Element layout: thread t, word jj in 0..3, lane c: idx = jj*4096 + 4*t + c.
// Candidate key: (r_bits<<32) | (e>0)<<16 | (16383 - idx).
// NOTE: r = |e|*(1-inhib) can be NEGATIVE (inhib grows toward 20). All max /
// threshold logic must clamp to 0 before any unsigned-bits comparison.
// Final-mask fill (total-order top_k, -0.0 < +0.0): selected positives,
// then non-selected e>0 ascending, then non-selected e<0 ascending.
// ---------------------------------------------------------------------------
__global__ void __launch_bounds__(NTH, 1) scan_kernel(float* __restrict__ out)
{
    __shared__ unsigned long long s_ckey[CAP];
    __shared__ unsigned long long s_selkey[KSEL];
    __shared__ unsigned s_selbit[H / 32];      // 512 words
    __shared__ unsigned s_red[32];
    __shared__ int      s_wcnt[32];
    __shared__ int      s_fcnt[2][32];
    __shared__ float    s_T;

    const int t = threadIdx.x, lane = t & 31, wp = t >> 5;
    const unsigned lt = (1u << lane) - 1u;

    float inhib[16];
#pragma unroll
    for (int u = 0; u < 16; u++) inhib[u] = 0.f;
    if (t == 0) s_T = -1.f;

    int pb = 0;                    // parity for s_fcnt double buffer

    for (int row = 0; row < BATCH; row++) {
        const float* erow = g_enc + (size_t)row * H;
        float* orow = out + (size_t)row * H;

        // ---- phase A: clear bitmap, load row, refracted, block max ----
        if (t < H / 32) s_selbit[t] = 0u;

        float r[16];
        unsigned pmask = 0;
        unsigned rmu = 0;
#pragma unroll
        for (int jj = 0; jj < 4; jj++) {
            float4 v = *(const float4*)(erow + jj * 4096 + 4 * t);
            float e[4] = {v.x, v.y, v.z, v.w};
#pragma unroll
            for (int c = 0; c < 4; c++) {
                int u = jj * 4 + c;
                float rr = fabsf(e[c]) * (1.0f - inhib[u]);
                r[u] = rr;
                // clamp to 0 first: uint-bits order is only monotone for >= 0
                rmu = max(rmu, __float_as_uint(fmaxf(rr, 0.f)));
                pmask |= (unsigned)(e[c] > 0.f) << u;
            }
        }
        rmu = __reduce_max_sync(0xffffffffu, rmu);
        if (lane == 0) s_red[wp] = rmu;
        __syncthreads();                               // bar A
        unsigned rm = 0;
#pragma unroll
        for (int w = 0; w < 32; w++) rm = max(rm, s_red[w]);
        float rmax = __uint_as_float(rm);

        float T = s_T;
        if (!(T > 0.f && T < rmax)) T = 0.5f * rmax;
        float Tlo = 0.f, Thi = rmax;
        int M, wbase;

        // ---- gather pass 1: counts only (no atomics) + bisection retry ----
        int iters = 0;
        for (;;) {
            int wcnt = 0;
#pragma unroll
            for (int u = 0; u < 16; u++)
                wcnt += __popc(__ballot_sync(0xffffffffu, r[u] > T));
            if (lane == 0) s_wcnt[wp] = wcnt;
            __syncthreads();                           // bar G1
            wbase = 0; M = 0;
#pragma unroll
            for (int w = 0; w < 32; w++) {
                int c = s_wcnt[w];
                if (w < wp) wbase += c;
                M += c;
            }
            if (M >= KSEL && M <= CAP) break;
            if (++iters >= 100 && M >= KSEL) break;    // safety net (unreachable)
            if (M > CAP) Tlo = T; else Thi = T;
            T = 0.5f * (Tlo + Thi);
            __syncthreads();                           // protect s_wcnt reuse
        }
        if (M > CAP) M = CAP;                          // only via safety net

        // ---- gather pass 2: write candidates at exclusive offsets ----
        {
            int base = wbase;
#pragma unroll
            for (int u = 0; u < 16; u++) {
                unsigned bal = __ballot_sync(0xffffffffu, r[u] > T);
                if (r[u] > T) {
                    int pos = base + __popc(bal & lt);
                    if (pos < CAP) {
                        unsigned idx = (unsigned)((u >> 2) * 4096 + 4 * t + (u & 3));
                        unsigned lowk = (((pmask >> u) & 1u) << 16) | (16383u - idx);
                        s_ckey[pos] =
                            ((unsigned long long)__float_as_uint(r[u]) << 32) | lowk;
                    }
                }
                base += __popc(bal);
            }
        }
        __syncthreads();                               // bar G2: ckey ready

        // ---- exact rank selection; winners emit key/bitmap/output ----
        if (t < M) {
            unsigned long long k = s_ckey[t];
            int rank = 0;
            for (int d = 0; d < M; d++) rank += (s_ckey[d] > k);
            if (rank < KSEL) {
                s_selkey[rank] = k;
                unsigned idx = 16383u - ((unsigned)k & 0x3FFFu);
                atomicOr(&s_selbit[idx >> 5], 1u << (idx & 31));  // spread, cheap
                if ((k >> 16) & 1ull) orow[idx] = 1.0f;
            }
        }
        __syncthreads();                               // bar R: selkey ready

        // ---- p-count + inhibition update from selkeys (broadcast LDS) ----
        int cnt = 0;
#pragma unroll
        for (int u = 0; u < 16; u++) inhib[u] *= DECAY;
        for (int s = 0; s < KSEL; s++) {
            unsigned long long k = s_selkey[s];
            cnt += (int)((k >> 16) & 1ull);
            unsigned idx = 16383u - ((unsigned)k & 0x3FFFu);
            if ((int)((idx & 4095u) >> 2) == t)
                inhib[(idx >> 12) * 4 + (idx & 3u)] += 1.0f;
        }
        if (t == 0)
            s_T = __uint_as_float((unsigned)(s_selkey[KSEL - 1] >> 32)) * 0.85f;

        // ---- fill from registers + bitmap: pass0 e>0 asc, pass1 e<0 asc ----
        for (int pass = 0; pass < 2 && cnt < KSEL; pass++) {
            for (int q = 0; q < 16; q++) {
                const int jj = q >> 2;
                const bool active = ((t >> 8) == (q & 3));
                unsigned cb = 0;
                if (active) {
#pragma unroll
                    for (int c = 0; c < 4; c++) {
                        int u = jj * 4 + c;
                        unsigned idx = (unsigned)(jj * 4096 + 4 * t + c);
                        bool sel = (s_selbit[idx >> 5] >> (idx & 31)) & 1u;
                        bool pbit = (pmask >> u) & 1u;
                        bool cand = !sel && (pass == 0 ? pbit : !pbit);
                        cb |= (unsigned)cand << c;
                    }
                }
                int pre = 0, wtot = 0;
#pragma unroll
                for (int c = 0; c < 4; c++) {
                    unsigned bal = __ballot_sync(0xffffffffu, (cb >> c) & 1u);
                    pre  += __popc(bal & lt);
                    wtot += __popc(bal);
                }
                if (lane == 0) s_fcnt[pb][wp] = wtot;
                __syncthreads();                       // one bar per chunk
                int gpre = 0, gtot = 0;
                const int wb = 8 * (q & 3);
#pragma unroll
                for (int w = 0; w < 8; w++) {
                    int cc = s_fcnt[pb][wb + w];
                    if (wb + w < wp) gpre += cc;
                    gtot += cc;
                }
                if (active && cb) {
                    int b2 = cnt + gpre + pre, within = 0;
#pragma unroll
                    for (int c = 0; c < 4; c++) {
                        if ((cb >> c) & 1u) {
                            if (b2 + within < KSEL)
                                orow[jj * 4096 + 4 * t + c] = 1.0f;
                            within++;
                        }
                    }
                }
                cnt += gtot;                           // uniform across block
                pb ^= 1;
                if (cnt >= KSEL) break;
            }
        }
        __syncthreads();    // row end: orders bitmap clear / s_red / s_T reuse
    }
}

// ---------------------------------------------------------------------------
extern "C" void kernel_launch(void* const* d_in, const int* in_sizes, int n_in,
                              void* d_out, int out_size)
{
    const float* inputs = (const float*)d_in[0];   // [512, 2048]
    const float* W      = (const float*)d_in[1];   // [16384, 2048]
    float* out          = (float*)d_out;           // [512, 16384]

    const int n4 = (BATCH * H) / 4;
    zero_out_kernel<<<(n4 + 255) / 256, 256>>>((float4*)out, n4);

    dim3 ggrid(H / GBN, BATCH / GBM);              // (128, 4)
    sgemm_nt_kernel<<<ggrid, 256>>>(inputs, W);

    scan_kernel<<<1, NTH>>>(out);
}

// round 14
// speedup vs baseline: 1.4281x; 1.4281x over previous
#include <cuda_runtime.h>
#include <cooperative_groups.h>
#include <cstdint>

namespace cg = cooperative_groups;

#define H      16384
#define BATCH  512
#define INSZ   2048
#define KSEL   64
#define DECAY  0.95f

#define NCTA   8
#define TPB    512
#define HP     (H / NCTA)      // 2048 elements per CTA
#define CAP    1024            // global candidate cap
#define PCAP   512             // per-CTA candidate cap

__device__ float g_enc[(size_t)BATCH * H];   // 32 MB scratch (no-alloc rule)

// ---------------------------------------------------------------------------
__global__ void zero_out_kernel(float4* __restrict__ out, int n4) {
    int i = blockIdx.x * blockDim.x + threadIdx.x;
    if (i < n4) out[i] = make_float4(0.f, 0.f, 0.f, 0.f);
}

// ---------------------------------------------------------------------------
// fp32 GEMM  C[m][n] = sum_k A[m][k] * W[n][k]; 128x128 tile, BK=16
// (round-8 baseline version — part of the 8653us best)
// ---------------------------------------------------------------------------
#define GBM 128
#define GBN 128
#define GBK 16

__global__ void __launch_bounds__(256) sgemm_nt_kernel(
    const float* __restrict__ A, const float* __restrict__ W)
{
    __shared__ float As[GBK][GBM];
    __shared__ float Bs[GBK][GBN];

    const int bn = blockIdx.x * GBN, bm = blockIdx.y * GBM;
    const int tid = threadIdx.x, tx = tid & 15, ty = tid >> 4;

    float acc[8][8];
#pragma unroll
    for (int i = 0; i < 8; i++)
#pragma unroll
        for (int j = 0; j < 8; j++) acc[i][j] = 0.f;

    for (int k0 = 0; k0 < INSZ; k0 += GBK) {
#pragma unroll
        for (int l = 0; l < 2; l++) {
            int q = tid + 256 * l, row = q >> 2, kk = (q & 3) * 4;
            float4 v = *(const float4*)&A[(bm + row) * INSZ + k0 + kk];
            As[kk][row] = v.x; As[kk + 1][row] = v.y;
            As[kk + 2][row] = v.z; As[kk + 3][row] = v.w;
        }
#pragma unroll
        for (int l = 0; l < 2; l++) {
            int q = tid + 256 * l, row = q >> 2, kk = (q & 3) * 4;
            float4 v = *(const float4*)&W[(bn + row) * INSZ + k0 + kk];
            Bs[kk][row] = v.x; Bs[kk + 1][row] = v.y;
            Bs[kk + 2][row] = v.z; Bs[kk + 3][row] = v.w;
        }
        __syncthreads();
#pragma unroll
        for (int k = 0; k < GBK; k++) {
            float a[8], b[8];
#pragma unroll
            for (int i = 0; i < 8; i++) a[i] = As[k][ty * 8 + i];
#pragma unroll
            for (int i = 0; i < 8; i++) b[i] = Bs[k][tx * 8 + i];
#pragma unroll
            for (int i = 0; i < 8; i++)
#pragma unroll
                for (int j = 0; j < 8; j++)
                    acc[i][j] = fmaf(a[i], b[j], acc[i][j]);
        }
        __syncthreads();
    }
#pragma unroll
    for (int i = 0; i < 8; i++) {
        int m = bm + ty * 8 + i;
#pragma unroll
        for (int j = 0; j < 8; j += 4)
            *(float4*)&g_enc[(size_t)m * H + bn + tx * 8 + j] =
                make_float4(acc[i][j], acc[i][j+1], acc[i][j+2], acc[i][j+3]);
    }
}

// ---------------------------------------------------------------------------
// Cluster-parallel sequential scan: 8 CTAs x 512 threads, H split 2048/CTA.
// Thread tid owns global indices base+4*tid+c (c=0..3) and their inhibition.
// Candidate key: (r_bits<<32) | (e>0)<<16 | (16383 - idx)  — identical to the
// passing round-12 kernel, so selection order semantics are unchanged.
// All CTAs execute identical scalar arithmetic on identical published data,
// so accept/bisect decisions and selkeys are bitwise-uniform across the
// cluster (required: every cluster.sync() is in uniform control flow).
// Final-mask fill (total-order top_k, -0.0 < +0.0): selected positives,
// then non-selected e>0 ascending, then non-selected e<0 ascending.
// ---------------------------------------------------------------------------
__global__ void __launch_bounds__(TPB, 1) __cluster_dims__(NCTA, 1, 1)
scan_kernel(float* __restrict__ out)
{
    // export blocks (read remotely by peers)
    __shared__ unsigned long long sx_ckey[2][PCAP];   // [row parity]
    __shared__ int      sx_cnt[2];                    // [bisection-iter parity]
    __shared__ int      sx_fc[2][2];                  // [row parity][pass]
    __shared__ unsigned sx_rmax;
    // local working storage
    __shared__ unsigned long long s_all[CAP];
    __shared__ unsigned long long s_selkey[KSEL];
    __shared__ unsigned s_selbit[HP / 32];            // 64 words
    __shared__ unsigned s_w[16], s_w2[16];
    __shared__ int      s_mir[16];

    cg::cluster_group cluster = cg::this_cluster();
    const int myrank = (int)cluster.block_rank();
    const int tid = threadIdx.x, lane = tid & 31, wp = tid >> 5;
    const unsigned full = 0xffffffffu;
    const unsigned lt = (1u << lane) - 1u;
    const int base = myrank * HP;

    float inhib[4] = {0.f, 0.f, 0.f, 0.f};
    float T_ws = -1.f;

    for (int row = 0; row < BATCH; row++) {
        const float* erow = g_enc + (size_t)row * H;
        float* orow = out + (size_t)row * H;
        const int pb = row & 1;

        if (tid < HP / 32) s_selbit[tid] = 0u;

        // ---- load slice + refracted ----
        float4 v = *(const float4*)(erow + base + 4 * tid);
        float e[4] = {v.x, v.y, v.z, v.w};
        float r[4];
        unsigned pmask = 0;
#pragma unroll
        for (int c = 0; c < 4; c++) {
            r[c] = fabsf(e[c]) * (1.0f - inhib[c]);
            pmask |= (unsigned)(e[c] > 0.f) << c;
        }

        float T = T_ws;
        float Tlo = 0.f, Thi = 0.f;
        bool haveHi = false;

        // ---- rmax path (row 0 / invalid warm start; uniform across CTAs) ----
        if (!(T > 0.f)) {
            unsigned m = 0;
#pragma unroll
            for (int c = 0; c < 4; c++)
                m = max(m, __float_as_uint(fmaxf(r[c], 0.f)));   // clamp FIRST
            m = __reduce_max_sync(full, m);
            if (lane == 0) s_w[wp] = m;
            __syncthreads();
            unsigned mm = 0;
#pragma unroll
            for (int w = 0; w < 16; w++) mm = max(mm, s_w[w]);
            if (tid == 0) sx_rmax = mm;
            cluster.sync();
            if (tid < NCTA)
                s_mir[tid] = (int)*cluster.map_shared_rank(&sx_rmax, tid);
            __syncthreads();
            unsigned g = 0;
#pragma unroll
            for (int c = 0; c < NCTA; c++) g = max(g, (unsigned)s_mir[c]);
            float rmax = __uint_as_float(g);
            Thi = rmax; haveHi = true; T = 0.5f * rmax;
        }

        // ---- bisection: publish local count, mirror-read, decide ----
        int M, it = 0, mycnt;
        for (;;) {
            int wc = 0;
#pragma unroll
            for (int c = 0; c < 4; c++)
                wc += __popc(__ballot_sync(full, r[c] > T));
            if (lane == 0) s_w[wp] = (unsigned)wc;
            __syncthreads();
            int tot = 0;
#pragma unroll
            for (int w = 0; w < 16; w++) tot += (int)s_w[w];
            if (tid == 0) sx_cnt[it & 1] = tot;
            cluster.sync();
            if (tid < NCTA)
                s_mir[tid] = *cluster.map_shared_rank(&sx_cnt[it & 1], tid);
            __syncthreads();
            M = 0; int maxloc = 0;
#pragma unroll
            for (int c = 0; c < NCTA; c++) {
                int x = s_mir[c];
                M += x; maxloc = max(maxloc, x);
            }
            mycnt = tot;
            if (M >= KSEL && M <= CAP && maxloc <= PCAP) break;
            if (M > CAP || maxloc > PCAP) {
                Tlo = T; T = haveHi ? 0.5f * (Tlo + Thi) : T * 2.0f;
            } else {
                Thi = T; haveHi = true; T = 0.5f * (Tlo + Thi);
            }
            it++;
        }

        // ---- write local candidates (s_w still holds final warp counts) ----
        {
            int wbase = 0;
#pragma unroll
            for (int w = 0; w < 16; w++) if (w < wp) wbase += (int)s_w[w];
            int cum = 0;
#pragma unroll
            for (int c = 0; c < 4; c++) {
                unsigned bal = __ballot_sync(full, r[c] > T);
                if (r[c] > T) {
                    int pos = wbase + cum + __popc(bal & lt);
                    unsigned idx = (unsigned)(base + 4 * tid + c);
                    sx_ckey[pb][pos] =
                        ((unsigned long long)__float_as_uint(r[c]) << 32)
                        | (((pmask >> c) & 1u) << 16) | (16383u - idx);
                }
                cum += __popc(bal);
            }
        }
        cluster.sync();                         // candidates visible

        // ---- gather all candidates (order by CTA rank; rank-invariant) ----
        {
            int b = 0;
            for (int c = 0; c < NCTA; c++) {
                int cnt = s_mir[c];
                const unsigned long long* rp =
                    cluster.map_shared_rank(&sx_ckey[pb][0], c);
                for (int i = tid; i < cnt; i += TPB) s_all[b + i] = rp[i];
                b += cnt;
            }
        }
        __syncthreads();

        // ---- redundant exact rank selection (each CTA full copy) ----
        for (int tt = tid; tt < M; tt += TPB) {
            unsigned long long k = s_all[tt];
            int rank = 0;
            for (int d = 0; d < M; d++) rank += (s_all[d] > k);
            if (rank < KSEL) {
                s_selkey[rank] = k;
                unsigned idx = 16383u - ((unsigned)k & 0x3FFFu);
                if ((int)(idx >> 11) == myrank) {     // owner emits
                    unsigned l = idx - (unsigned)base;
                    atomicOr(&s_selbit[l >> 5], 1u << (l & 31));
                    if ((k >> 16) & 1ull) orow[idx] = 1.0f;
                }
            }
        }
        __syncthreads();

        // ---- p-count + inhibition + warm start (identical on all CTAs) ----
        int p = 0;
#pragma unroll
        for (int c = 0; c < 4; c++) inhib[c] *= DECAY;
        for (int s = 0; s < KSEL; s++) {
            unsigned long long k = s_selkey[s];
            p += (int)((k >> 16) & 1ull);
            int l = (int)(16383u - ((unsigned)k & 0x3FFFu)) - base;
            if ((l >> 2) == tid)                 // negative/foreign l never match
                inhib[l & 3] += 1.0f;
        }
        T_ws = __uint_as_float((unsigned)(s_selkey[KSEL - 1] >> 32)) * 0.85f;

        // ---- fill: pass0 = non-sel e>0 asc, pass1 = non-sel e<0 asc ----
        if (p < KSEL) {                          // p identical on all CTAs
            unsigned cb0 = 0, cb1 = 0;
#pragma unroll
            for (int c = 0; c < 4; c++) {
                int l = 4 * tid + c;
                bool sel = (s_selbit[l >> 5] >> (l & 31)) & 1u;
                bool pbit = (pmask >> c) & 1u;
                cb0 |= (unsigned)(!sel &&  pbit) << c;
                cb1 |= (unsigned)(!sel && !pbit) << c;
            }
            int n0 = __popc(cb0), n1 = __popc(cb1);
            int e0 = n0, e1 = n1;                 // lane inclusive scans
#pragma unroll
            for (int o = 1; o < 32; o <<= 1) {
                int v0 = __shfl_up_sync(full, e0, o);
                int v1 = __shfl_up_sync(full, e1, o);
                if (lane >= o) { e0 += v0; e1 += v1; }
            }
            int i0 = e0 - n0, i1 = e1 - n1;       // exclusive
            if (lane == 31) { s_w[wp] = (unsigned)e0; s_w2[wp] = (unsigned)e1; }
            __syncthreads();
            int wb0 = 0, wb1 = 0, t0 = 0, t1 = 0;
#pragma unroll
            for (int w = 0; w < 16; w++) {
                int a = (int)s_w[w], b2 = (int)s_w2[w];
                if (w < wp) { wb0 += a; wb1 += b2; }
                t0 += a; t1 += b2;
            }
            if (tid == 0) { sx_fc[pb][0] = t0; sx_fc[pb][1] = t1; }
            cluster.sync();
            if (tid < NCTA)
                s_mir[tid] = *cluster.map_shared_rank(&sx_fc[pb][0], tid);
            else if (tid < 2 * NCTA)
                s_mir[tid] = *cluster.map_shared_rank(&sx_fc[pb][1], tid - NCTA);
            __syncthreads();
            int start0 = p, sum0 = 0;
#pragma unroll
            for (int c = 0; c < NCTA; c++) {
                if (c < myrank) start0 += s_mir[c];
                sum0 += s_mir[c];
            }
            int start1 = p + sum0;
#pragma unroll
            for (int c = 0; c < NCTA; c++)
                if (c < myrank) start1 += s_mir[NCTA + c];

            int pos = start0 + wb0 + i0;
#pragma unroll
            for (int c = 0; c < 4; c++)
                if ((cb0 >> c) & 1u) {
                    if (pos < KSEL) orow[base + 4 * tid + c] = 1.0f;
                    pos++;
                }
            pos = start1 + wb1 + i1;
#pragma unroll
            for (int c = 0; c < 4; c++)
                if ((cb1 >> c) & 1u) {
                    if (pos < KSEL) orow[base + 4 * tid + c] = 1.0f;
                    pos++;
                }
        }
        __syncthreads();   // CTA-local: protect selbit/s_w reuse next row
    }
}

// ---------------------------------------------------------------------------
extern "C" void kernel_launch(void* const* d_in, const int* in_sizes, int n_in,
                              void* d_out, int out_size)
{
    const float* inputs = (const float*)d_in[0];   // [512, 2048]
    const float* W      = (const float*)d_in[1];   // [16384, 2048]
    float* out          = (float*)d_out;           // [512, 16384]

    const int n4 = (BATCH * H) / 4;
    zero_out_kernel<<<(n4 + 255) / 256, 256>>>((float4*)out, n4);

    dim3 ggrid(H / GBN, BATCH / GBM);              // (128, 4)
    sgemm_nt_kernel<<<ggrid, 256>>>(inputs, W);

    scan_kernel<<<NCTA, TPB>>>(out);               // 1 cluster of 8 CTAs
}